// round 12
// baseline (speedup 1.0000x reference)
#include <cuda_runtime.h>
#include <cuda_fp16.h>
#include <math.h>

#define NU 100000
#define NI 50000
#define DD 64
#define ES 800000
#define EUI 1000000
#define EIU 1000000
#define ETOT (ES + EUI + EIU)
#define NROWS (2 * NU + NI)
#define NSCANBLK ((NROWS + 2047) / 2048)
#define NEMB8 ((NU + NI) * 8)           // uint4 records per embedding set
#define ALPHA_LRELU 0.2f
#define CDIV(a,b) (((a)+(b)-1)/(b))

// ---------------- scratch (device globals; no runtime allocation) -------------
__device__ int2  g_meta[ETOT];                 // {col, half2(e1,e2)} — 8B/edge
__device__ int   g_cnt[NROWS];                 // zero at load; re-zeroed by scan
__device__ int   g_rowptr[NROWS + 1];
__device__ int   g_cursor[NROWS];
__device__ unsigned long long g_status[NSCANBLK];
__device__ uint4 g_h16[3 * NEMB8];             // fp16 node embeddings (128B/node):
                                               // set0: u0,i0  set1: u1,i1  set2: u2,i2

// ---------------- helpers ------------------------------------------------------
__device__ __forceinline__ float warp_sum(float v) {
    #pragma unroll
    for (int o = 16; o; o >>= 1) v += __shfl_xor_sync(0xffffffffu, v, o);
    return v;
}
__device__ __forceinline__ float red8(float v) {    // butterfly within 8-lane group
    #pragma unroll
    for (int o = 4; o; o >>= 1) v += __shfl_xor_sync(0xffffffffu, v, o);
    return v;
}
__device__ __forceinline__ float att_scalar(float dot, float b1, float w2, float b2) {
    float h = tanhf(dot + b1);
    float g = h * w2 + b2;
    g = g > 0.f ? g : ALPHA_LRELU * g;
    return expf(g);
}
__device__ __forceinline__ __half2 i2h2(int v) { return *reinterpret_cast<__half2*>(&v); }
__device__ __forceinline__ int h2i(__half2 v) { return *reinterpret_cast<int*>(&v); }
__device__ __forceinline__ uint2 f42h(float4 v) {
    uint2 g;
    *reinterpret_cast<__half2*>(&g.x) = __floats2half2_rn(v.x, v.y);
    *reinterpret_cast<__half2*>(&g.y) = __floats2half2_rn(v.z, v.w);
    return g;
}
__device__ __forceinline__ float4 h2f4u2(uint2 g) {
    float2 a = __half22float2(*reinterpret_cast<const __half2*>(&g.x));
    float2 b = __half22float2(*reinterpret_cast<const __half2*>(&g.y));
    return make_float4(a.x, a.y, b.x, b.y);
}

// ---------------- preprocessing --------------------------------------------------
// hist + status reset + fp16 conversion of u0/i0 (uint4 records)
__global__ void k_hist_all(const int4* __restrict__ sn_row, const int4* __restrict__ ci_row,
                           const int4* __restrict__ ic_row, int* __restrict__ cnt,
                           unsigned long long* __restrict__ status,
                           const float4* __restrict__ u_emb, const float4* __restrict__ i_emb,
                           uint4* __restrict__ h16) {
    int i = blockIdx.x * blockDim.x + threadIdx.x;
    int gsz = gridDim.x * blockDim.x;
    for (int t = i; t < NEMB8; t += gsz) {
        float4 v0, v1;
        if (t < NU * 8) { v0 = __ldg(u_emb + 2 * t); v1 = __ldg(u_emb + 2 * t + 1); }
        else { int tt = t - NU * 8; v0 = __ldg(i_emb + 2 * tt); v1 = __ldg(i_emb + 2 * tt + 1); }
        uint2 a = f42h(v0), b = f42h(v1);
        h16[t] = make_uint4(a.x, a.y, b.x, b.y);
    }
    if (i < NSCANBLK) status[i] = 0ull;
    int4 r; int base;
    if (i < ES/4) { r = sn_row[i]; base = 0; }
    else if (i < (ES+EUI)/4) { r = ci_row[i - ES/4]; base = NU; }
    else if (i < ETOT/4) { r = ic_row[i - (ES+EUI)/4]; base = 2*NU; }
    else return;
    atomicAdd(cnt + base + r.x, 1);
    atomicAdd(cnt + base + r.y, 1);
    atomicAdd(cnt + base + r.z, 1);
    atomicAdd(cnt + base + r.w, 1);
}

__global__ void __launch_bounds__(1024) k_scan(int* __restrict__ cnt,
                                               int* __restrict__ rowptr,
                                               int* __restrict__ cursor,
                                               unsigned long long* status) {
    __shared__ int sh[1024];
    __shared__ int s_prefix;
    int t = threadIdx.x, b = blockIdx.x;
    int i0 = b * 2048 + 2 * t;
    int c0 = (i0 < NROWS) ? cnt[i0] : 0;
    int c1 = (i0 + 1 < NROWS) ? cnt[i0 + 1] : 0;
    if (i0 < NROWS) cnt[i0] = 0;
    if (i0 + 1 < NROWS) cnt[i0 + 1] = 0;
    int p = c0 + c1;
    sh[t] = p;
    __syncthreads();
    #pragma unroll
    for (int off = 1; off < 1024; off <<= 1) {
        int add = (t >= off) ? sh[t - off] : 0;
        __syncthreads();
        sh[t] += add;
        __syncthreads();
    }
    if (t == 1023) {
        long long total = sh[1023];
        atomicExch(status + b, ((unsigned long long)total << 2) | 1ull);
        long long prefix = 0;
        for (int pb = b - 1; pb >= 0; ) {
            unsigned long long s = *((volatile unsigned long long*)(status + pb));
            unsigned st = (unsigned)(s & 3ull);
            if (st == 0u) continue;
            prefix += (long long)(s >> 2);
            if (st == 2u) break;
            pb--;
        }
        atomicExch(status + b, ((unsigned long long)(prefix + total) << 2) | 2ull);
        s_prefix = (int)prefix;
    }
    __syncthreads();
    int excl = sh[t] - p + s_prefix;
    if (i0 < NROWS)     { rowptr[i0] = excl;          cursor[i0] = excl; }
    if (i0 + 1 < NROWS) { rowptr[i0 + 1] = excl + c0; cursor[i0 + 1] = excl + c0; }
    if (b == 0 && t == 0) rowptr[NROWS] = ETOT;
}

__global__ void k_scatter_all(const int4* __restrict__ sn_row, const int4* __restrict__ sn_col,
                              const float4* __restrict__ snii1, const float4* __restrict__ snii2,
                              const int4* __restrict__ ci_row, const int4* __restrict__ ci_col,
                              const float4* __restrict__ ciii1, const float4* __restrict__ ciii2,
                              const int4* __restrict__ ic_row, const int4* __restrict__ ic_col,
                              const float4* __restrict__ icii1, const float4* __restrict__ icii2,
                              const float* __restrict__ law, const float* __restrict__ lab,
                              int* __restrict__ cursor, int2* __restrict__ meta) {
    int i = blockIdx.x * blockDim.x + threadIdx.x;
    int4 r, c; float4 a, b; int base, j1, j2;
    if (i < ES/4) {
        r = sn_row[i]; c = sn_col[i]; a = snii1[i]; b = snii2[i]; base = 0; j1 = 0; j2 = 1;
    } else if (i < (ES+EUI)/4) {
        int ii = i - ES/4;
        r = ci_row[ii]; c = ci_col[ii]; a = ciii1[ii]; b = ciii2[ii]; base = NU; j1 = 2; j2 = 3;
    } else if (i < ETOT/4) {
        int ii = i - (ES+EUI)/4;
        r = ic_row[ii]; c = ic_col[ii]; a = icii1[ii]; b = icii2[ii]; base = 2*NU; j1 = 4; j2 = 5;
    } else return;
    float w1 = law[j1], b1 = lab[j1], w2 = law[j2], b2 = lab[j2];
    int rr[4] = {r.x, r.y, r.z, r.w};
    int cc[4] = {c.x, c.y, c.z, c.w};
    float aa[4] = {a.x, a.y, a.z, a.w};
    float bb[4] = {b.x, b.y, b.z, b.w};
    #pragma unroll
    for (int k = 0; k < 4; k++) {
        float x1 = aa[k] * w1 + b1;
        float x2 = bb[k] * w2 + b2;
        // exp(exp(sigmoid(x))) in [e, e^e]; softmax max-shift unnecessary; fp16-safe range
        float e1 = expf(expf(1.f / (1.f + expf(-x1))));
        float e2 = expf(expf(1.f / (1.f + expf(-x2))));
        int pos = atomicAdd(cursor + base + rr[k], 1);
        __half2 hw = __floats2half2_rn(e1, e2);   // low = e1, high = e2
        int2 rec;
        rec.x = cc[k];
        rec.y = *reinterpret_cast<int*>(&hw);
        meta[pos] = rec;
    }
}

// ---------------- SpMM primitives: 8 lanes/edge, LDG.128, HFMA2 -----------------
// quarter = lane>>3 handles edges k+quarter; q = lane&7 covers 16B of the 128B row.
// Out-of-row lanes carry h=0 from the batch load -> shuffled weights self-mask
// (shfl indices <= 31 by construction). Row sum via batch-phase warp_sum (exact).
// Results (fp32, normalized): out[8] floats per lane, valid in lanes 0-7.

template<int COMP>
__device__ __forceinline__ void spmm_dual(const int2* __restrict__ meta,
                                          int s1, int e1, int s2, int e2,
                                          const uint4* __restrict__ x1,
                                          const uint4* __restrict__ x2,
                                          int lane, float* out1, float* out2) {
    __half2 a1[4], a2[4];
    #pragma unroll
    for (int j = 0; j < 4; j++) { a1[j] = __float2half2_rn(0.f); a2[j] = a1[j]; }
    float ws1 = 0.f, ws2 = 0.f;
    const int quarter = lane >> 3;
    const int q = lane & 7;
    const uint4* x1q = x1 + q;
    const uint4* x2q = x2 + q;
    int base1 = s1, base2 = s2;
    while (base1 < e1 || base2 < e2) {
        int c1 = 0, c2 = 0, h1 = 0, h2v = 0;
        int j1 = base1 + lane, j2 = base2 + lane;
        if (j1 < e1) {
            int2 m = __ldg(meta + j1);
            c1 = m.x; h1 = m.y;
            ws1 += COMP ? __high2float(i2h2(h1)) : __low2float(i2h2(h1));
        }
        if (j2 < e2) {
            int2 m = __ldg(meta + j2);
            c2 = m.x; h2v = m.y;
            ws2 += COMP ? __high2float(i2h2(h2v)) : __low2float(i2h2(h2v));
        }
        int d1 = e1 - base1, d2 = e2 - base2;
        int rem = min(32, max(d1, d2));
        for (int k = 0; k < rem; k += 4) {
            int iA = k + quarter;                       // <= 28+3 = 31
            int   cA1 = __shfl_sync(0xffffffffu, c1, iA);
            int   hA1 = __shfl_sync(0xffffffffu, h1, iA);
            int   cA2 = __shfl_sync(0xffffffffu, c2, iA);
            int   hA2 = __shfl_sync(0xffffffffu, h2v, iA);
            __half2 wA1 = COMP ? __highs2half2(i2h2(hA1), i2h2(hA1))
                               : __lows2half2(i2h2(hA1), i2h2(hA1));
            __half2 wA2 = COMP ? __highs2half2(i2h2(hA2), i2h2(hA2))
                               : __lows2half2(i2h2(hA2), i2h2(hA2));
            uint4 xa = __ldg(x1q + ((size_t)cA1 << 3));
            uint4 xb = __ldg(x2q + ((size_t)cA2 << 3));
            a1[0] = __hfma2(wA1, i2h2((int)xa.x), a1[0]);
            a1[1] = __hfma2(wA1, i2h2((int)xa.y), a1[1]);
            a1[2] = __hfma2(wA1, i2h2((int)xa.z), a1[2]);
            a1[3] = __hfma2(wA1, i2h2((int)xa.w), a1[3]);
            a2[0] = __hfma2(wA2, i2h2((int)xb.x), a2[0]);
            a2[1] = __hfma2(wA2, i2h2((int)xb.y), a2[1]);
            a2[2] = __hfma2(wA2, i2h2((int)xb.z), a2[2]);
            a2[3] = __hfma2(wA2, i2h2((int)xb.w), a2[3]);
        }
        base1 += 32; base2 += 32;
    }
    float inv1 = 1.f / (warp_sum(ws1) + 1e-12f);
    float inv2 = 1.f / (warp_sum(ws2) + 1e-12f);
    // reduce across quarters (lanes q, q+8, q+16, q+24)
    #pragma unroll
    for (int j = 0; j < 4; j++) {
        int r;
        r = __shfl_down_sync(0xffffffffu, h2i(a1[j]), 16); a1[j] = __hadd2(a1[j], i2h2(r));
        r = __shfl_down_sync(0xffffffffu, h2i(a1[j]), 8);  a1[j] = __hadd2(a1[j], i2h2(r));
        r = __shfl_down_sync(0xffffffffu, h2i(a2[j]), 16); a2[j] = __hadd2(a2[j], i2h2(r));
        r = __shfl_down_sync(0xffffffffu, h2i(a2[j]), 8);  a2[j] = __hadd2(a2[j], i2h2(r));
    }
    #pragma unroll
    for (int j = 0; j < 4; j++) {
        float2 f1 = __half22float2(a1[j]);
        float2 f2 = __half22float2(a2[j]);
        out1[2*j] = f1.x * inv1; out1[2*j+1] = f1.y * inv1;
        out2[2*j] = f2.x * inv2; out2[2*j+1] = f2.y * inv2;
    }
}

template<int COMP>
__device__ __forceinline__ void spmm_single(const int2* __restrict__ meta,
                                            int s, int e,
                                            const uint4* __restrict__ x16,
                                            int lane, float* out) {
    __half2 a0[4], a1[4];
    #pragma unroll
    for (int j = 0; j < 4; j++) { a0[j] = __float2half2_rn(0.f); a1[j] = a0[j]; }
    float ws = 0.f;
    const int quarter = lane >> 3;
    const int q = lane & 7;
    const uint4* xq = x16 + q;
    for (int base = s; base < e; base += 32) {
        int j = base + lane;
        int c = 0, h = 0;
        if (j < e) {
            int2 m = __ldg(meta + j);
            c = m.x; h = m.y;
            ws += COMP ? __high2float(i2h2(h)) : __low2float(i2h2(h));
        }
        int rem = min(32, e - base);
        for (int k = 0; k < rem; k += 8) {
            int iA = k + quarter;                       // <= 24+3 = 27
            int iB = k + 4 + quarter;                   // <= 24+4+3 = 31
            int   cA = __shfl_sync(0xffffffffu, c, iA);
            int   hA = __shfl_sync(0xffffffffu, h, iA);
            int   cB = __shfl_sync(0xffffffffu, c, iB);
            int   hB = __shfl_sync(0xffffffffu, h, iB);
            __half2 wA = COMP ? __highs2half2(i2h2(hA), i2h2(hA))
                              : __lows2half2(i2h2(hA), i2h2(hA));
            __half2 wB = COMP ? __highs2half2(i2h2(hB), i2h2(hB))
                              : __lows2half2(i2h2(hB), i2h2(hB));
            uint4 xA = __ldg(xq + ((size_t)cA << 3));
            uint4 xB = __ldg(xq + ((size_t)cB << 3));
            a0[0] = __hfma2(wA, i2h2((int)xA.x), a0[0]);
            a0[1] = __hfma2(wA, i2h2((int)xA.y), a0[1]);
            a0[2] = __hfma2(wA, i2h2((int)xA.z), a0[2]);
            a0[3] = __hfma2(wA, i2h2((int)xA.w), a0[3]);
            a1[0] = __hfma2(wB, i2h2((int)xB.x), a1[0]);
            a1[1] = __hfma2(wB, i2h2((int)xB.y), a1[1]);
            a1[2] = __hfma2(wB, i2h2((int)xB.z), a1[2]);
            a1[3] = __hfma2(wB, i2h2((int)xB.w), a1[3]);
        }
    }
    float inv = 1.f / (warp_sum(ws) + 1e-12f);
    #pragma unroll
    for (int j = 0; j < 4; j++) {
        a0[j] = __hadd2(a0[j], a1[j]);
        int r;
        r = __shfl_down_sync(0xffffffffu, h2i(a0[j]), 16); a0[j] = __hadd2(a0[j], i2h2(r));
        r = __shfl_down_sync(0xffffffffu, h2i(a0[j]), 8);  a0[j] = __hadd2(a0[j], i2h2(r));
    }
    #pragma unroll
    for (int j = 0; j < 4; j++) {
        float2 f = __half22float2(a0[j]);
        out[2*j] = f.x * inv; out[2*j+1] = f.y * inv;
    }
}

// ---------------- merged layer kernel (8-lane groups in epilogue) ---------------
template<int COMP>
__global__ void __launch_bounds__(256) k_layer(const uint4* __restrict__ uprev,
                                               const uint4* __restrict__ iprev,
                                               const int2* __restrict__ meta,
                                               const int* __restrict__ rowptr,
                                               const float* __restrict__ a1W,
                                               const float* __restrict__ a1b,
                                               const float* __restrict__ a2w,
                                               const float* __restrict__ a2b,
                                               int ku, int ki,
                                               uint4* __restrict__ u_out,
                                               uint4* __restrict__ i_out) {
    int warp = (blockIdx.x * blockDim.x + threadIdx.x) >> 5;
    int lane = threadIdx.x & 31;
    int q = lane & 7;
    if (warp < NU) {
        int node = warp;
        int s_sn = __ldg(rowptr + node),      e_sn = __ldg(rowptr + node + 1);
        int s_ci = __ldg(rowptr + NU + node), e_ci = __ldg(rowptr + NU + node + 1);
        float fu[8], fi[8];
        spmm_dual<COMP>(meta, s_sn, e_sn, s_ci, e_ci, uprev, iprev, lane, fu, fi);
        int k = ku;
        const float* Wa = a1W + (size_t)k * 128;
        const float* Wb = Wa + 128;
        if (lane < 8) {
            uint4 ur = __ldg(uprev + (size_t)node * 8 + q);
            float4 ua = h2f4u2(make_uint2(ur.x, ur.y));
            float4 ub = h2f4u2(make_uint2(ur.z, ur.w));
            float u[8] = {ua.x, ua.y, ua.z, ua.w, ub.x, ub.y, ub.z, ub.w};
            const float4* WaQ = (const float4*)(Wa + q * 8);
            const float4* WaF = (const float4*)(Wa + 64 + q * 8);
            const float4* WbQ = (const float4*)(Wb + q * 8);
            const float4* WbF = (const float4*)(Wb + 64 + q * 8);
            float4 wa0 = __ldg(WaQ), wa0b = __ldg(WaQ + 1);
            float4 wa1 = __ldg(WaF), wa1b = __ldg(WaF + 1);
            float4 wb0 = __ldg(WbQ), wb0b = __ldg(WbQ + 1);
            float4 wb1 = __ldg(WbF), wb1b = __ldg(WbF + 1);
            float dint = u[0]*wa0.x + u[1]*wa0.y + u[2]*wa0.z + u[3]*wa0.w
                       + u[4]*wa0b.x + u[5]*wa0b.y + u[6]*wa0b.z + u[7]*wa0b.w
                       + fi[0]*wa1.x + fi[1]*wa1.y + fi[2]*wa1.z + fi[3]*wa1.w
                       + fi[4]*wa1b.x + fi[5]*wa1b.y + fi[6]*wa1b.z + fi[7]*wa1b.w;
            float dsoc = u[0]*wb0.x + u[1]*wb0.y + u[2]*wb0.z + u[3]*wb0.w
                       + u[4]*wb0b.x + u[5]*wb0b.y + u[6]*wb0b.z + u[7]*wb0b.w
                       + fu[0]*wb1.x + fu[1]*wb1.y + fu[2]*wb1.z + fu[3]*wb1.w
                       + fu[4]*wb1b.x + fu[5]*wb1b.y + fu[6]*wb1b.z + fu[7]*wb1b.w;
            dint = red8(dint); dsoc = red8(dsoc);
            float aint = att_scalar(dint, a1b[k],     a2w[k],     a2b[k])     + 0.7f;
            float asoc = att_scalar(dsoc, a1b[k + 1], a2w[k + 1], a2b[k + 1]) + 0.3f;
            float sden = aint + asoc;
            float wi = 0.5f * aint / sden, wsoc = 0.5f * asoc / sden;
            float o[8];
            #pragma unroll
            for (int j = 0; j < 8; j++)
                o[j] = 0.5f * u[j] + wi * fi[j] + wsoc * fu[j];
            uint2 g0 = f42h(make_float4(o[0], o[1], o[2], o[3]));
            uint2 g1 = f42h(make_float4(o[4], o[5], o[6], o[7]));
            u_out[(size_t)node * 8 + q] = make_uint4(g0.x, g0.y, g1.x, g1.y);
        }
    } else {
        int node = warp - NU;
        if (node >= NI) return;
        int s_ic = __ldg(rowptr + 2 * NU + node), e_ic = __ldg(rowptr + 2 * NU + node + 1);
        float f[8];
        spmm_single<COMP>(meta, s_ic, e_ic, uprev, lane, f);
        int k = ki;
        const float* Wa = a1W + (size_t)k * 128;
        const float* Wb = Wa + 128;
        if (lane < 8) {
            uint4 ir = __ldg(iprev + (size_t)node * 8 + q);
            float4 ia = h2f4u2(make_uint2(ir.x, ir.y));
            float4 ib = h2f4u2(make_uint2(ir.z, ir.w));
            float it[8] = {ia.x, ia.y, ia.z, ia.w, ib.x, ib.y, ib.z, ib.w};
            const float4* WaQ = (const float4*)(Wa + q * 8);
            const float4* WaF = (const float4*)(Wa + 64 + q * 8);
            const float4* WbQ = (const float4*)(Wb + q * 8);
            const float4* WbF = (const float4*)(Wb + 64 + q * 8);
            float4 wa0 = __ldg(WaQ), wa0b = __ldg(WaQ + 1);
            float4 wa1 = __ldg(WaF), wa1b = __ldg(WaF + 1);
            float4 wb0 = __ldg(WbQ), wb0b = __ldg(WbQ + 1);
            float4 wb1 = __ldg(WbF), wb1b = __ldg(WbF + 1);
            float dself = it[0]*(wa0.x+wa1.x) + it[1]*(wa0.y+wa1.y)
                        + it[2]*(wa0.z+wa1.z) + it[3]*(wa0.w+wa1.w)
                        + it[4]*(wa0b.x+wa1b.x) + it[5]*(wa0b.y+wa1b.y)
                        + it[6]*(wa0b.z+wa1b.z) + it[7]*(wa0b.w+wa1b.w);
            float dcust = it[0]*wb0.x + it[1]*wb0.y + it[2]*wb0.z + it[3]*wb0.w
                        + it[4]*wb0b.x + it[5]*wb0b.y + it[6]*wb0b.z + it[7]*wb0b.w
                        + f[0]*wb1.x + f[1]*wb1.y + f[2]*wb1.z + f[3]*wb1.w
                        + f[4]*wb1b.x + f[5]*wb1b.y + f[6]*wb1b.z + f[7]*wb1b.w;
            dself = red8(dself); dcust = red8(dcust);
            float aself = att_scalar(dself, a1b[k],     a2w[k],     a2b[k])     + 1.0f;
            float acust = att_scalar(dcust, a1b[k + 1], a2w[k + 1], a2b[k + 1]) + 1.0f;
            float sden = aself + acust;
            float wsf = aself / sden, wcu = acust / sden;
            float o[8];
            #pragma unroll
            for (int j = 0; j < 8; j++)
                o[j] = wsf * it[j] + wcu * f[j];
            uint2 g0 = f42h(make_float4(o[0], o[1], o[2], o[3]));
            uint2 g1 = f42h(make_float4(o[4], o[5], o[6], o[7]));
            i_out[(size_t)node * 8 + q] = make_uint4(g0.x, g0.y, g1.x, g1.y);
        }
    }
}

// final scorer: warp per (user, item) pair; u0/i0 fp32, layer outputs fp16 (uint2 view)
__global__ void __launch_bounds__(256) k_final(const float4* __restrict__ u0,
                                               const uint2* __restrict__ u1,
                                               const uint2* __restrict__ u2,
                                               const float4* __restrict__ i0,
                                               const uint2* __restrict__ i1,
                                               const uint2* __restrict__ i2,
                                               const int* __restrict__ uidx,
                                               const int* __restrict__ iidx,
                                               float* __restrict__ out, int B) {
    int b = (blockIdx.x * blockDim.x + threadIdx.x) >> 5;
    int lane = threadIdx.x & 31;
    if (b >= B) return;
    float d = 0.f;
    if (lane < 16) {
        size_t uo = (size_t)__ldg(uidx + b) * 16 + lane;
        size_t io = (size_t)__ldg(iidx + b) * 16 + lane;
        float4 a0 = __ldg(u0 + uo),         c0 = __ldg(i0 + io);
        float4 a1 = h2f4u2(__ldg(u1 + uo)), c1 = h2f4u2(__ldg(i1 + io));
        float4 a2 = h2f4u2(__ldg(u2 + uo)), c2 = h2f4u2(__ldg(i2 + io));
        d = a0.x*c0.x + a0.y*c0.y + a0.z*c0.z + a0.w*c0.w
          + a1.x*c1.x + a1.y*c1.y + a1.z*c1.z + a1.w*c1.w
          + a2.x*c2.x + a2.y*c2.y + a2.z*c2.z + a2.w*c2.w;
    }
    d = warp_sum(d);
    if (lane == 0) out[b] = 1.f / (1.f + expf(-d));
}

// ---------------- launch ------------------------------------------------------
extern "C" void kernel_launch(void* const* d_in, const int* in_sizes, int n_in,
                              void* d_out, int out_size) {
    const float* u_emb = (const float*)d_in[0];
    const float* i_emb = (const float*)d_in[1];
    const float* snii1 = (const float*)d_in[2];
    const float* snii2 = (const float*)d_in[3];
    const float* ciii1 = (const float*)d_in[4];
    const float* ciii2 = (const float*)d_in[5];
    const float* icii1 = (const float*)d_in[6];
    const float* icii2 = (const float*)d_in[7];
    const float* law   = (const float*)d_in[8];
    const float* lab   = (const float*)d_in[9];
    const float* a1W   = (const float*)d_in[10];
    const float* a1b   = (const float*)d_in[11];
    const float* a2w   = (const float*)d_in[12];
    const float* a2b   = (const float*)d_in[13];
    const int* sn_row  = (const int*)d_in[14];
    const int* sn_col  = (const int*)d_in[15];
    const int* ci_row  = (const int*)d_in[16];
    const int* ci_col  = (const int*)d_in[17];
    const int* ic_row  = (const int*)d_in[18];
    const int* ic_col  = (const int*)d_in[19];
    const int* uidx    = (const int*)d_in[20];
    const int* iidx    = (const int*)d_in[21];
    float* out = (float*)d_out;
    int B = out_size;

    int2 *meta; int *cnt, *rowptr, *cursor; unsigned long long *status; uint4 *h16;
    cudaGetSymbolAddress((void**)&meta, g_meta);
    cudaGetSymbolAddress((void**)&cnt, g_cnt);
    cudaGetSymbolAddress((void**)&rowptr, g_rowptr);
    cudaGetSymbolAddress((void**)&cursor, g_cursor);
    cudaGetSymbolAddress((void**)&status, g_status);
    cudaGetSymbolAddress((void**)&h16, g_h16);

    uint4* u0_8 = h16;
    uint4* i0_8 = u0_8 + (size_t)NU * 8;
    uint4* u1_8 = h16 + NEMB8;
    uint4* i1_8 = u1_8 + (size_t)NU * 8;
    uint4* u2_8 = h16 + 2 * NEMB8;
    uint4* i2_8 = u2_8 + (size_t)NU * 8;

    const int T = 256;

    // ---- CSR build + edge weights + fp16 conversion ----
    k_hist_all<<<CDIV(ETOT/4, T), T>>>((const int4*)sn_row, (const int4*)ci_row,
                                       (const int4*)ic_row, cnt, status,
                                       (const float4*)u_emb, (const float4*)i_emb, h16);
    k_scan<<<NSCANBLK, 1024>>>(cnt, rowptr, cursor, status);
    k_scatter_all<<<CDIV(ETOT/4, T), T>>>((const int4*)sn_row, (const int4*)sn_col,
                                          (const float4*)snii1, (const float4*)snii2,
                                          (const int4*)ci_row, (const int4*)ci_col,
                                          (const float4*)ciii1, (const float4*)ciii2,
                                          (const int4*)ic_row, (const int4*)ic_col,
                                          (const float4*)icii1, (const float4*)icii2,
                                          law, lab, cursor, meta);

    // ---- layers (merged user+item) ----
    int layer_warps = NU + NI;
    k_layer<0><<<CDIV(layer_warps * 32, T), T>>>(u0_8, i0_8, meta, rowptr,
                                                 a1W, a1b, a2w, a2b, 0, 4, u1_8, i1_8);
    k_layer<1><<<CDIV(layer_warps * 32, T), T>>>(u1_8, i1_8, meta, rowptr,
                                                 a1W, a1b, a2w, a2b, 2, 6, u2_8, i2_8);

    // ---- final ----
    k_final<<<CDIV(B * 32, T), T>>>((const float4*)u_emb, (const uint2*)u1_8, (const uint2*)u2_8,
                                    (const float4*)i_emb, (const uint2*)i1_8, (const uint2*)i2_8,
                                    uidx, iidx, out, B);
}

// round 13
// speedup vs baseline: 1.1945x; 1.1945x over previous
#include <cuda_runtime.h>
#include <cuda_fp16.h>
#include <math.h>

#define NU 100000
#define NI 50000
#define DD 64
#define ES 800000
#define EUI 1000000
#define EIU 1000000
#define ETOT (ES + EUI + EIU)
#define NROWS (2 * NU + NI)
#define NSCANBLK ((NROWS + 2047) / 2048)
#define NEMB16 ((NU + NI) * 16)         // uint2 records per embedding set
#define ALPHA_LRELU 0.2f
#define CDIV(a,b) (((a)+(b)-1)/(b))

// ---------------- scratch (device globals; no runtime allocation) -------------
__device__ int2  g_meta[ETOT];                 // {col, half2(e1,e2)} — 8B/edge
__device__ int   g_cnt[NROWS];                 // zero at load; re-zeroed by scan
__device__ int   g_rowptr[NROWS + 1];
__device__ int   g_cursor[NROWS];
__device__ unsigned long long g_status[NSCANBLK];
__device__ uint2 g_h16[3 * NEMB16];            // fp16 node embeddings:
                                               // set0: u0,i0  set1: u1,i1  set2: u2,i2

// ---------------- helpers ------------------------------------------------------
__device__ __forceinline__ float warp_sum(float v) {
    #pragma unroll
    for (int o = 16; o; o >>= 1) v += __shfl_xor_sync(0xffffffffu, v, o);
    return v;
}
__device__ __forceinline__ float red16(float v) {
    #pragma unroll
    for (int o = 8; o; o >>= 1) v += __shfl_xor_sync(0xffffffffu, v, o);
    return v;
}
__device__ __forceinline__ float fast_tanh(float x) {
    float y;
    asm("tanh.approx.f32 %0, %1;" : "=f"(y) : "f"(x));
    return y;
}
__device__ __forceinline__ float fast_sigmoid(float x) {
    return __fdividef(1.f, 1.f + __expf(-x));
}
__device__ __forceinline__ float att_scalar(float dot, float b1, float w2, float b2) {
    float h = fast_tanh(dot + b1);
    float g = h * w2 + b2;
    g = g > 0.f ? g : ALPHA_LRELU * g;
    return __expf(g);
}
__device__ __forceinline__ float4 h2f4(uint2 g) {
    float2 a = __half22float2(*reinterpret_cast<const __half2*>(&g.x));
    float2 b = __half22float2(*reinterpret_cast<const __half2*>(&g.y));
    return make_float4(a.x, a.y, b.x, b.y);
}
__device__ __forceinline__ uint2 f42h(float4 v) {
    uint2 g;
    *reinterpret_cast<__half2*>(&g.x) = __floats2half2_rn(v.x, v.y);
    *reinterpret_cast<__half2*>(&g.y) = __floats2half2_rn(v.z, v.w);
    return g;
}
__device__ __forceinline__ __half2 i2h2(int v) {
    return *reinterpret_cast<__half2*>(&v);
}

// ---------------- preprocessing (R11, fast-math logits) -------------------------
__global__ void k_hist_all(const int4* __restrict__ sn_row, const int4* __restrict__ ci_row,
                           const int4* __restrict__ ic_row, int* __restrict__ cnt,
                           unsigned long long* __restrict__ status,
                           const float4* __restrict__ u_emb, const float4* __restrict__ i_emb,
                           uint2* __restrict__ h16) {
    int i = blockIdx.x * blockDim.x + threadIdx.x;
    int gsz = gridDim.x * blockDim.x;
    for (int t = i; t < NEMB16; t += gsz) {
        float4 v = (t < NU * 16) ? __ldg(u_emb + t) : __ldg(i_emb + t - NU * 16);
        h16[t] = f42h(v);
    }
    if (i < NSCANBLK) status[i] = 0ull;
    int4 r; int base;
    if (i < ES/4) { r = sn_row[i]; base = 0; }
    else if (i < (ES+EUI)/4) { r = ci_row[i - ES/4]; base = NU; }
    else if (i < ETOT/4) { r = ic_row[i - (ES+EUI)/4]; base = 2*NU; }
    else return;
    atomicAdd(cnt + base + r.x, 1);
    atomicAdd(cnt + base + r.y, 1);
    atomicAdd(cnt + base + r.z, 1);
    atomicAdd(cnt + base + r.w, 1);
}

__global__ void __launch_bounds__(1024) k_scan(int* __restrict__ cnt,
                                               int* __restrict__ rowptr,
                                               int* __restrict__ cursor,
                                               unsigned long long* status) {
    __shared__ int sh[1024];
    __shared__ int s_prefix;
    int t = threadIdx.x, b = blockIdx.x;
    int i0 = b * 2048 + 2 * t;
    int c0 = (i0 < NROWS) ? cnt[i0] : 0;
    int c1 = (i0 + 1 < NROWS) ? cnt[i0 + 1] : 0;
    if (i0 < NROWS) cnt[i0] = 0;
    if (i0 + 1 < NROWS) cnt[i0 + 1] = 0;
    int p = c0 + c1;
    sh[t] = p;
    __syncthreads();
    #pragma unroll
    for (int off = 1; off < 1024; off <<= 1) {
        int add = (t >= off) ? sh[t - off] : 0;
        __syncthreads();
        sh[t] += add;
        __syncthreads();
    }
    if (t == 1023) {
        long long total = sh[1023];
        atomicExch(status + b, ((unsigned long long)total << 2) | 1ull);
        long long prefix = 0;
        for (int pb = b - 1; pb >= 0; ) {
            unsigned long long s = *((volatile unsigned long long*)(status + pb));
            unsigned st = (unsigned)(s & 3ull);
            if (st == 0u) continue;
            prefix += (long long)(s >> 2);
            if (st == 2u) break;
            pb--;
        }
        atomicExch(status + b, ((unsigned long long)(prefix + total) << 2) | 2ull);
        s_prefix = (int)prefix;
    }
    __syncthreads();
    int excl = sh[t] - p + s_prefix;
    if (i0 < NROWS)     { rowptr[i0] = excl;          cursor[i0] = excl; }
    if (i0 + 1 < NROWS) { rowptr[i0 + 1] = excl + c0; cursor[i0 + 1] = excl + c0; }
    if (b == 0 && t == 0) rowptr[NROWS] = ETOT;
}

__global__ void k_scatter_all(const int4* __restrict__ sn_row, const int4* __restrict__ sn_col,
                              const float4* __restrict__ snii1, const float4* __restrict__ snii2,
                              const int4* __restrict__ ci_row, const int4* __restrict__ ci_col,
                              const float4* __restrict__ ciii1, const float4* __restrict__ ciii2,
                              const int4* __restrict__ ic_row, const int4* __restrict__ ic_col,
                              const float4* __restrict__ icii1, const float4* __restrict__ icii2,
                              const float* __restrict__ law, const float* __restrict__ lab,
                              int* __restrict__ cursor, int2* __restrict__ meta) {
    int i = blockIdx.x * blockDim.x + threadIdx.x;
    int4 r, c; float4 a, b; int base, j1, j2;
    if (i < ES/4) {
        r = sn_row[i]; c = sn_col[i]; a = snii1[i]; b = snii2[i]; base = 0; j1 = 0; j2 = 1;
    } else if (i < (ES+EUI)/4) {
        int ii = i - ES/4;
        r = ci_row[ii]; c = ci_col[ii]; a = ciii1[ii]; b = ciii2[ii]; base = NU; j1 = 2; j2 = 3;
    } else if (i < ETOT/4) {
        int ii = i - (ES+EUI)/4;
        r = ic_row[ii]; c = ic_col[ii]; a = icii1[ii]; b = icii2[ii]; base = 2*NU; j1 = 4; j2 = 5;
    } else return;
    float w1 = law[j1], b1 = lab[j1], w2 = law[j2], b2 = lab[j2];
    int rr[4] = {r.x, r.y, r.z, r.w};
    int cc[4] = {c.x, c.y, c.z, c.w};
    float aa[4] = {a.x, a.y, a.z, a.w};
    float bb[4] = {b.x, b.y, b.z, b.w};
    #pragma unroll
    for (int k = 0; k < 4; k++) {
        float x1 = aa[k] * w1 + b1;
        float x2 = bb[k] * w2 + b2;
        // exp(exp(sigmoid(x))) in [e, e^e]; softmax max-shift unnecessary; fp16-safe range
        float e1 = __expf(__expf(fast_sigmoid(x1)));
        float e2 = __expf(__expf(fast_sigmoid(x2)));
        int pos = atomicAdd(cursor + base + rr[k], 1);
        __half2 hw = __floats2half2_rn(e1, e2);   // low = e1, high = e2
        int2 rec;
        rec.x = cc[k];
        rec.y = *reinterpret_cast<int*>(&hw);
        meta[pos] = rec;
    }
}

// ---------------- SpMM primitives: R11 proven form (HFMA2, 16 lanes/edge) -------
template<int COMP>
__device__ __forceinline__ void spmm_dual(const int2* __restrict__ meta,
                                          int s1, int e1, int s2, int e2,
                                          const uint2* __restrict__ x1,
                                          const uint2* __restrict__ x2,
                                          int lane, float4& o1, float4& o2) {
    __half2 a1lo = __float2half2_rn(0.f), a1hi = a1lo;
    __half2 a2lo = a1lo, a2hi = a1lo;
    float ws1 = 0.f, ws2 = 0.f;
    const int half = lane >> 4;
    const int q = lane & 15;
    const uint2* x1q = x1 + q;
    const uint2* x2q = x2 + q;
    int base1 = s1, base2 = s2;
    while (base1 < e1 || base2 < e2) {
        int c1 = 0, c2 = 0, h1 = 0, h2v = 0;
        int j1 = base1 + lane, j2 = base2 + lane;
        if (j1 < e1) {
            int2 m = __ldg(meta + j1);
            c1 = m.x; h1 = m.y;
            ws1 += COMP ? __high2float(i2h2(h1)) : __low2float(i2h2(h1));
        }
        if (j2 < e2) {
            int2 m = __ldg(meta + j2);
            c2 = m.x; h2v = m.y;
            ws2 += COMP ? __high2float(i2h2(h2v)) : __low2float(i2h2(h2v));
        }
        int d1 = e1 - base1, d2 = e2 - base2;
        int rem = min(32, max(d1, d2));
        for (int k = 0; k < rem; k += 2) {
            int iA = k + half;                          // <= 31 always
            int   cA1 = __shfl_sync(0xffffffffu, c1, iA);
            int   hA1 = __shfl_sync(0xffffffffu, h1, iA);
            int   cA2 = __shfl_sync(0xffffffffu, c2, iA);
            int   hA2 = __shfl_sync(0xffffffffu, h2v, iA);
            __half2 wA1 = COMP ? __highs2half2(i2h2(hA1), i2h2(hA1))
                               : __lows2half2(i2h2(hA1), i2h2(hA1));
            __half2 wA2 = COMP ? __highs2half2(i2h2(hA2), i2h2(hA2))
                               : __lows2half2(i2h2(hA2), i2h2(hA2));
            uint2 xa = __ldg(x1q + ((size_t)cA1 << 4));
            uint2 xb = __ldg(x2q + ((size_t)cA2 << 4));
            a1lo = __hfma2(wA1, i2h2((int)xa.x), a1lo);
            a1hi = __hfma2(wA1, i2h2((int)xa.y), a1hi);
            a2lo = __hfma2(wA2, i2h2((int)xb.x), a2lo);
            a2hi = __hfma2(wA2, i2h2((int)xb.y), a2hi);
        }
        base1 += 32; base2 += 32;
    }
    float inv1 = __fdividef(1.f, warp_sum(ws1) + 1e-12f);
    float inv2 = __fdividef(1.f, warp_sum(ws2) + 1e-12f);
    int r;
    r = __shfl_down_sync(0xffffffffu, *(int*)&a1lo, 16); a1lo = __hadd2(a1lo, i2h2(r));
    r = __shfl_down_sync(0xffffffffu, *(int*)&a1hi, 16); a1hi = __hadd2(a1hi, i2h2(r));
    r = __shfl_down_sync(0xffffffffu, *(int*)&a2lo, 16); a2lo = __hadd2(a2lo, i2h2(r));
    r = __shfl_down_sync(0xffffffffu, *(int*)&a2hi, 16); a2hi = __hadd2(a2hi, i2h2(r));
    float2 f1a = __half22float2(a1lo), f1b = __half22float2(a1hi);
    float2 f2a = __half22float2(a2lo), f2b = __half22float2(a2hi);
    o1 = make_float4(f1a.x * inv1, f1a.y * inv1, f1b.x * inv1, f1b.y * inv1);
    o2 = make_float4(f2a.x * inv2, f2a.y * inv2, f2b.x * inv2, f2b.y * inv2);
}

template<int COMP>
__device__ __forceinline__ float4 spmm_single(const int2* __restrict__ meta,
                                              int s, int e,
                                              const uint2* __restrict__ x16, int lane) {
    __half2 a0lo = __float2half2_rn(0.f), a0hi = a0lo;
    __half2 a1lo = a0lo, a1hi = a0lo;
    float ws = 0.f;
    const int half = lane >> 4;
    const int q = lane & 15;
    const uint2* xq = x16 + q;
    for (int base = s; base < e; base += 32) {
        int j = base + lane;
        int c = 0, h = 0;
        if (j < e) {
            int2 m = __ldg(meta + j);
            c = m.x; h = m.y;
            ws += COMP ? __high2float(i2h2(h)) : __low2float(i2h2(h));
        }
        int rem = min(32, e - base);
        for (int k = 0; k < rem; k += 4) {
            int iA = k + half;
            int iB = k + 2 + half;                      // k<=28 -> iB <= 31
            int   cA = __shfl_sync(0xffffffffu, c, iA);
            int   hA = __shfl_sync(0xffffffffu, h, iA);
            int   cB = __shfl_sync(0xffffffffu, c, iB);
            int   hB = __shfl_sync(0xffffffffu, h, iB);
            __half2 wA = COMP ? __highs2half2(i2h2(hA), i2h2(hA))
                              : __lows2half2(i2h2(hA), i2h2(hA));
            __half2 wB = COMP ? __highs2half2(i2h2(hB), i2h2(hB))
                              : __lows2half2(i2h2(hB), i2h2(hB));
            uint2 xA = __ldg(xq + ((size_t)cA << 4));
            uint2 xB = __ldg(xq + ((size_t)cB << 4));
            a0lo = __hfma2(wA, i2h2((int)xA.x), a0lo);
            a0hi = __hfma2(wA, i2h2((int)xA.y), a0hi);
            a1lo = __hfma2(wB, i2h2((int)xB.x), a1lo);
            a1hi = __hfma2(wB, i2h2((int)xB.y), a1hi);
        }
    }
    float inv = __fdividef(1.f, warp_sum(ws) + 1e-12f);
    __half2 lo = __hadd2(a0lo, a1lo);
    __half2 hi = __hadd2(a0hi, a1hi);
    int r;
    r = __shfl_down_sync(0xffffffffu, *(int*)&lo, 16); lo = __hadd2(lo, i2h2(r));
    r = __shfl_down_sync(0xffffffffu, *(int*)&hi, 16); hi = __hadd2(hi, i2h2(r));
    float2 fa = __half22float2(lo), fb = __half22float2(hi);
    return make_float4(fa.x * inv, fa.y * inv, fb.x * inv, fb.y * inv);
}

// ---------------- merged layer kernel (R11 structure) ----------------------------
template<int COMP>
__global__ void __launch_bounds__(256) k_layer(const uint2* __restrict__ uprev,
                                               const uint2* __restrict__ iprev,
                                               const int2* __restrict__ meta,
                                               const int* __restrict__ rowptr,
                                               const float* __restrict__ a1W,
                                               const float* __restrict__ a1b,
                                               const float* __restrict__ a2w,
                                               const float* __restrict__ a2b,
                                               int ku, int ki,
                                               uint2* __restrict__ u_out,
                                               uint2* __restrict__ i_out) {
    int warp = (blockIdx.x * blockDim.x + threadIdx.x) >> 5;
    int lane = threadIdx.x & 31;
    int q = lane & 15;
    if (warp < NU) {
        int node = warp;
        int s_sn = __ldg(rowptr + node),      e_sn = __ldg(rowptr + node + 1);
        int s_ci = __ldg(rowptr + NU + node), e_ci = __ldg(rowptr + NU + node + 1);
        float4 fu, fi;
        spmm_dual<COMP>(meta, s_sn, e_sn, s_ci, e_ci, uprev, iprev, lane, fu, fi);
        int k = ku;
        const float4* Wa = (const float4*)(a1W + (size_t)k * 128);
        const float4* Wb = Wa + 32;
        if (lane < 16) {
            float4 u = h2f4(__ldg(uprev + (size_t)node * 16 + q));
            float4 wa0 = __ldg(Wa + q), wa1 = __ldg(Wa + 16 + q);
            float4 wb0 = __ldg(Wb + q), wb1 = __ldg(Wb + 16 + q);
            float dint = u.x*wa0.x + u.y*wa0.y + u.z*wa0.z + u.w*wa0.w
                       + fi.x*wa1.x + fi.y*wa1.y + fi.z*wa1.z + fi.w*wa1.w;
            float dsoc = u.x*wb0.x + u.y*wb0.y + u.z*wb0.z + u.w*wb0.w
                       + fu.x*wb1.x + fu.y*wb1.y + fu.z*wb1.z + fu.w*wb1.w;
            dint = red16(dint); dsoc = red16(dsoc);
            float aint = att_scalar(dint, a1b[k],     a2w[k],     a2b[k])     + 0.7f;
            float asoc = att_scalar(dsoc, a1b[k + 1], a2w[k + 1], a2b[k + 1]) + 0.3f;
            float invs = __fdividef(0.5f, aint + asoc);
            float wi = aint * invs, wsoc = asoc * invs;
            float4 o;
            o.x = 0.5f * u.x + wi * fi.x + wsoc * fu.x;
            o.y = 0.5f * u.y + wi * fi.y + wsoc * fu.y;
            o.z = 0.5f * u.z + wi * fi.z + wsoc * fu.z;
            o.w = 0.5f * u.w + wi * fi.w + wsoc * fu.w;
            u_out[(size_t)node * 16 + q] = f42h(o);
        }
    } else {
        int node = warp - NU;
        if (node >= NI) return;
        int s_ic = __ldg(rowptr + 2 * NU + node), e_ic = __ldg(rowptr + 2 * NU + node + 1);
        float4 f = spmm_single<COMP>(meta, s_ic, e_ic, uprev, lane);
        int k = ki;
        const float4* Wa = (const float4*)(a1W + (size_t)k * 128);
        const float4* Wb = Wa + 32;
        if (lane < 16) {
            float4 it = h2f4(__ldg(iprev + (size_t)node * 16 + q));
            float4 wa0 = __ldg(Wa + q), wa1 = __ldg(Wa + 16 + q);
            float4 wb0 = __ldg(Wb + q), wb1 = __ldg(Wb + 16 + q);
            float dself = it.x*(wa0.x+wa1.x) + it.y*(wa0.y+wa1.y)
                        + it.z*(wa0.z+wa1.z) + it.w*(wa0.w+wa1.w);
            float dcust = it.x*wb0.x + it.y*wb0.y + it.z*wb0.z + it.w*wb0.w
                        + f.x*wb1.x + f.y*wb1.y + f.z*wb1.z + f.w*wb1.w;
            dself = red16(dself); dcust = red16(dcust);
            float aself = att_scalar(dself, a1b[k],     a2w[k],     a2b[k])     + 1.0f;
            float acust = att_scalar(dcust, a1b[k + 1], a2w[k + 1], a2b[k + 1]) + 1.0f;
            float invs = __fdividef(1.f, aself + acust);
            float wsf = aself * invs, wcu = acust * invs;
            float4 o;
            o.x = wsf * it.x + wcu * f.x;
            o.y = wsf * it.y + wcu * f.y;
            o.z = wsf * it.z + wcu * f.z;
            o.w = wsf * it.w + wcu * f.w;
            i_out[(size_t)node * 16 + q] = f42h(o);
        }
    }
}

// final scorer: warp per (user, item) pair; u0/i0 fp32, layer outputs fp16
__global__ void __launch_bounds__(256) k_final(const float4* __restrict__ u0,
                                               const uint2* __restrict__ u1,
                                               const uint2* __restrict__ u2,
                                               const float4* __restrict__ i0,
                                               const uint2* __restrict__ i1,
                                               const uint2* __restrict__ i2,
                                               const int* __restrict__ uidx,
                                               const int* __restrict__ iidx,
                                               float* __restrict__ out, int B) {
    int b = (blockIdx.x * blockDim.x + threadIdx.x) >> 5;
    int lane = threadIdx.x & 31;
    if (b >= B) return;
    float d = 0.f;
    if (lane < 16) {
        size_t uo = (size_t)__ldg(uidx + b) * 16 + lane;
        size_t io = (size_t)__ldg(iidx + b) * 16 + lane;
        float4 a0 = __ldg(u0 + uo),       c0 = __ldg(i0 + io);
        float4 a1 = h2f4(__ldg(u1 + uo)), c1 = h2f4(__ldg(i1 + io));
        float4 a2 = h2f4(__ldg(u2 + uo)), c2 = h2f4(__ldg(i2 + io));
        d = a0.x*c0.x + a0.y*c0.y + a0.z*c0.z + a0.w*c0.w
          + a1.x*c1.x + a1.y*c1.y + a1.z*c1.z + a1.w*c1.w
          + a2.x*c2.x + a2.y*c2.y + a2.z*c2.z + a2.w*c2.w;
    }
    d = warp_sum(d);
    if (lane == 0) out[b] = fast_sigmoid(d);
}

// ---------------- launch ------------------------------------------------------
extern "C" void kernel_launch(void* const* d_in, const int* in_sizes, int n_in,
                              void* d_out, int out_size) {
    const float* u_emb = (const float*)d_in[0];
    const float* i_emb = (const float*)d_in[1];
    const float* snii1 = (const float*)d_in[2];
    const float* snii2 = (const float*)d_in[3];
    const float* ciii1 = (const float*)d_in[4];
    const float* ciii2 = (const float*)d_in[5];
    const float* icii1 = (const float*)d_in[6];
    const float* icii2 = (const float*)d_in[7];
    const float* law   = (const float*)d_in[8];
    const float* lab   = (const float*)d_in[9];
    const float* a1W   = (const float*)d_in[10];
    const float* a1b   = (const float*)d_in[11];
    const float* a2w   = (const float*)d_in[12];
    const float* a2b   = (const float*)d_in[13];
    const int* sn_row  = (const int*)d_in[14];
    const int* sn_col  = (const int*)d_in[15];
    const int* ci_row  = (const int*)d_in[16];
    const int* ci_col  = (const int*)d_in[17];
    const int* ic_row  = (const int*)d_in[18];
    const int* ic_col  = (const int*)d_in[19];
    const int* uidx    = (const int*)d_in[20];
    const int* iidx    = (const int*)d_in[21];
    float* out = (float*)d_out;
    int B = out_size;

    int2 *meta; int *cnt, *rowptr, *cursor; unsigned long long *status; uint2 *h16;
    cudaGetSymbolAddress((void**)&meta, g_meta);
    cudaGetSymbolAddress((void**)&cnt, g_cnt);
    cudaGetSymbolAddress((void**)&rowptr, g_rowptr);
    cudaGetSymbolAddress((void**)&cursor, g_cursor);
    cudaGetSymbolAddress((void**)&status, g_status);
    cudaGetSymbolAddress((void**)&h16, g_h16);

    uint2* u0_16 = h16;
    uint2* i0_16 = u0_16 + (size_t)NU * 16;
    uint2* u1_16 = h16 + NEMB16;
    uint2* i1_16 = u1_16 + (size_t)NU * 16;
    uint2* u2_16 = h16 + 2 * NEMB16;
    uint2* i2_16 = u2_16 + (size_t)NU * 16;

    const int T = 256;

    // ---- CSR build + edge weights + fp16 conversion ----
    k_hist_all<<<CDIV(ETOT/4, T), T>>>((const int4*)sn_row, (const int4*)ci_row,
                                       (const int4*)ic_row, cnt, status,
                                       (const float4*)u_emb, (const float4*)i_emb, h16);
    k_scan<<<NSCANBLK, 1024>>>(cnt, rowptr, cursor, status);
    k_scatter_all<<<CDIV(ETOT/4, T), T>>>((const int4*)sn_row, (const int4*)sn_col,
                                          (const float4*)snii1, (const float4*)snii2,
                                          (const int4*)ci_row, (const int4*)ci_col,
                                          (const float4*)ciii1, (const float4*)ciii2,
                                          (const int4*)ic_row, (const int4*)ic_col,
                                          (const float4*)icii1, (const float4*)icii2,
                                          law, lab, cursor, meta);

    // ---- layers (merged user+item, R11 grid) ----
    int layer_warps = NU + NI;
    k_layer<0><<<CDIV(layer_warps * 32, T), T>>>(u0_16, i0_16, meta, rowptr,
                                                 a1W, a1b, a2w, a2b, 0, 4, u1_16, i1_16);
    k_layer<1><<<CDIV(layer_warps * 32, T), T>>>(u1_16, i1_16, meta, rowptr,
                                                 a1W, a1b, a2w, a2b, 2, 6, u2_16, i2_16);

    // ---- final ----
    k_final<<<CDIV(B * 32, T), T>>>((const float4*)u_emb, u1_16, u2_16,
                                    (const float4*)i_emb, i1_16, i2_16,
                                    uidx, iidx, out, B);
}